// round 9
// baseline (speedup 1.0000x reference)
#include <cstdint>
#include <cstddef>
#include <cuda_runtime.h>
#include <cuda_fp16.h>
#include <mma.h>

using namespace nvcuda;

#define BSZ 128
#define TT  128
#define INP 64
#define HID 512
#define G4  2048
#define HB  (BSZ*HID)
#define NCTA 128

// dynamic smem map (bytes):
//   [0, 132096)        weights: 64 rows x 1032 halves (stride 2064 B)
//   [132096, 165888)   A buffer 0: 64 rows x 264 halves (stride 528 B)
//   [165888, 199680)   A buffer 1
//   [199680, 216064)   smf: 64x64 float
#define WSTRH   1032
#define WSTRB   2064
#define ASTRH   264
#define ASTRB   528
#define ABUF0   132096
#define ABSZ    33792
#define SMFOFF  199680
#define SMEM_TOTAL 216064

// ---------------- device state ----------------
__device__ __align__(128) __half g_eWih0[G4*INP];
__device__ __align__(128) __half g_eWhh0[G4*HID];
__device__ __align__(128) __half g_eWih1[G4*HID];
__device__ __align__(128) __half g_eWhh1[G4*HID];
__device__ __align__(128) __half g_dWih0[G4*HID];
__device__ __align__(128) __half g_dWhh0[G4*HID];
__device__ __align__(128) __half g_dWih1[G4*HID];
__device__ __align__(128) __half g_dWhh1[G4*HID];
__device__ __align__(128) __half g_fcW[INP*HID];
__device__ float  g_be0[G4];
__device__ float  g_be1[G4];
__device__ float  g_bd0[G4];
__device__ float  g_bd1[G4];
__device__ __align__(128) __half g_x16[TT*BSZ*INP];
__device__ __align__(128) __half g_h0[2][HB];
__device__ __align__(128) __half g_h1[2][HB];
__device__ __align__(128) __half g_hd0[2][HB];
__device__ __align__(128) __half g_hd1[2][HB];
__device__ float  g_gx[BSZ*G4];
__device__ __align__(128) __half g_hs[TT*BSZ*HID];
__device__ unsigned g_ctr;
__device__ unsigned g_flag[8];   // [enc: bot0,bot1,top0,top1][dec: bot0,bot1,top0,top1]

// ---------------- prep ----------------
__global__ void prep_kernel(
    const float* __restrict__ x,
    const float* __restrict__ eWih0, const float* __restrict__ eWhh0,
    const float* __restrict__ ebih0, const float* __restrict__ ebhh0,
    const float* __restrict__ eWih1, const float* __restrict__ eWhh1,
    const float* __restrict__ ebih1, const float* __restrict__ ebhh1,
    const float* __restrict__ dWih0, const float* __restrict__ dWhh0,
    const float* __restrict__ dbih0, const float* __restrict__ dbhh0,
    const float* __restrict__ dWih1, const float* __restrict__ dWhh1,
    const float* __restrict__ dbih1, const float* __restrict__ dbhh1,
    const float* __restrict__ fcW)
{
    const long NP = 8822793;
    long stride = (long)gridDim.x * blockDim.x;
    for (long i = (long)blockIdx.x * blockDim.x + threadIdx.x; i < NP; i += stride) {
        long r = i;
        if (r < 131072)  { g_eWih0[r] = __float2half(eWih0[r]); continue; } r -= 131072;
        if (r < 1048576) { g_eWhh0[r] = __float2half(eWhh0[r]); continue; } r -= 1048576;
        if (r < 1048576) { g_eWih1[r] = __float2half(eWih1[r]); continue; } r -= 1048576;
        if (r < 1048576) { g_eWhh1[r] = __float2half(eWhh1[r]); continue; } r -= 1048576;
        if (r < 1048576) { g_dWih0[r] = __float2half(dWih0[r]); continue; } r -= 1048576;
        if (r < 1048576) { g_dWhh0[r] = __float2half(dWhh0[r]); continue; } r -= 1048576;
        if (r < 1048576) { g_dWih1[r] = __float2half(dWih1[r]); continue; } r -= 1048576;
        if (r < 1048576) { g_dWhh1[r] = __float2half(dWhh1[r]); continue; } r -= 1048576;
        if (r < 32768)   { g_fcW[r]   = __float2half(fcW[r]);   continue; } r -= 32768;
        if (r < 8192) {
            int which = (int)(r >> 11);
            int j = (int)(r & 2047);
            if      (which == 0) g_be0[j] = ebih0[j] + ebhh0[j];
            else if (which == 1) g_be1[j] = ebih1[j] + ebhh1[j];
            else if (which == 2) g_bd0[j] = dbih0[j] + dbhh0[j];
            else                 g_bd1[j] = dbih1[j] + dbhh1[j];
            continue;
        } r -= 8192;
        if (r < 1048576) {
            int t = (int)(r >> 13);
            int rem = (int)(r & 8191);
            int b = rem >> 6;
            int k = rem & 63;
            g_x16[r] = __float2half(x[(size_t)b * TT * INP + (size_t)t * INP + k]);
            continue;
        } r -= 1048576;
        if (r < 262144) {
            int which = (int)(r >> 16);
            int j = (int)(r & 65535);
            __half z = __float2half(0.f);
            if      (which == 0) g_h0[1][j]  = z;
            else if (which == 1) g_h1[1][j]  = z;
            else if (which == 2) g_hd0[1][j] = z;
            else                 g_hd1[1][j] = z;
            continue;
        } r -= 262144;
        {   // 9 sync words per replay
            if (r < 8) g_flag[r] = 0u;
            else       g_ctr = 0u;
        }
    }
}

// ---------------- helpers ----------------
__device__ __forceinline__ uint32_t smem_to_u32(const void* smem_ptr) {
    uint32_t addr;
    asm("{ .reg .u64 tmp; cvta.to.shared.u64 tmp, %1; cvt.u32.u64 %0, tmp; }"
        : "=r"(addr) : "l"(smem_ptr));
    return addr;
}
__device__ __forceinline__ void cp_async16(uint32_t dst_smem, const void* src) {
    asm volatile("cp.async.cg.shared.global [%0], [%1], 16;"
                 :: "r"(dst_smem), "l"(src) : "memory");
}
__device__ __forceinline__ void cp_async_commit() {
    asm volatile("cp.async.commit_group;" ::: "memory");
}
__device__ __forceinline__ void cp_async_wait0() {
    asm volatile("cp.async.wait_group 0;" ::: "memory");
}
__device__ __forceinline__ void cp_async_wait1() {
    asm volatile("cp.async.wait_group 1;" ::: "memory");
}
__device__ __forceinline__ float sigf(float v) { return 1.f / (1.f + __expf(-v)); }

// ---------------- sync primitives ----------------
// Full grid barrier (phase boundaries only)
__device__ __forceinline__ void grid_sync(unsigned target) {
    __syncthreads();
    if (threadIdx.x == 0) {
        __threadfence();
        atomicAdd(&g_ctr, 1u);
        volatile unsigned* cp = &g_ctr;
        while (*cp < target) { }
        __threadfence();
    }
    __syncthreads();
}

// Point-to-point dataflow wait on up to two group counters
__device__ __forceinline__ void wait2(unsigned* f1, unsigned v1,
                                      unsigned* f2, unsigned v2) {
    if (threadIdx.x == 0) {
        volatile unsigned* p1 = f1;
        volatile unsigned* p2 = f2;
        while (*p1 < v1) { }
        while (*p2 < v2) { }
        __threadfence();
    }
    __syncthreads();
}
// Publish completion of this CTA's step to its group counter
__device__ __forceinline__ void post_flag(unsigned* f) {
    __syncthreads();
    if (threadIdx.x == 0) {
        __threadfence();
        atomicAdd(f, 1u);
    }
}

// ---------------- stationary weight load ----------------
// smem row c (D-col c): weight row grow = (c&3)*512 + u0 + (c>>2); row = [W1 | W2]
__device__ void load_wsm(char* smraw, const __half* __restrict__ W1, int Kx,
                         const __half* __restrict__ W2, int u0) {
    int K = Kx + 512;
    int ng = K >> 3;
    int tot = 64 * ng;
    for (int idx = threadIdx.x; idx < tot; idx += 256) {
        int c = idx / ng;
        int gi = idx - c * ng;
        int k = gi << 3;
        int grow = (c & 3) * 512 + u0 + (c >> 2);
        uint4 v;
        if (k < Kx) v = *(const uint4*)(W1 + (size_t)grow * Kx + k);
        else        v = *(const uint4*)(W2 + (size_t)grow * 512 + (k - Kx));
        *(uint4*)(smraw + (size_t)c * WSTRB + ((size_t)k << 1)) = v;
    }
}

// ---------------- stage one A super-chunk [64 rows x (ke-kb) halves] ----------------
__device__ __forceinline__ void stage_chunk(uint32_t dst, int kb, int ke,
                                            const __half* __restrict__ s0, int ld0, int Kx,
                                            const __half* __restrict__ s1, int m0) {
    int ng = (ke - kb) >> 3;       // 16B granules per row: 32 or 8
    int tot = 64 * ng;
    for (int idx = threadIdx.x; idx < tot; idx += 256) {
        int r, gi;
        if (ng == 32) { r = idx >> 5; gi = idx & 31; }
        else          { r = idx >> 3; gi = idx & 7; }
        int k = kb + (gi << 3);
        const __half* src;
        if (k < Kx) src = s0 + (size_t)(m0 + r) * ld0 + k;
        else        src = s1 + (size_t)(m0 + r) * HID + (k - Kx);
        cp_async16(dst + (uint32_t)(r * ASTRB + (gi << 4)), src);
    }
}

// ---------------- one LSTM cell step (smem-staged, HMMA) ----------------
// CTA tile: 64 batch rows x 64 gate-cols (16 units x 4 gates, gate = col&3)
__device__ __forceinline__ void cell_step(
    char* smraw, uint32_t smb,
    const __half* __restrict__ s0, int ld0, int Kx,
    const __half* __restrict__ s1, int K,
    const float* badd, float* cst,
    __half* __restrict__ hout, __half* __restrict__ hsave,
    int m0, int u0, int mi, int ni, int uloc, int mb)
{
    wmma::fragment<wmma::accumulator, 16, 16, 16, float> acc0, acc1;
    wmma::fill_fragment(acc0, 0.f);
    wmma::fill_fragment(acc1, 0.f);
    wmma::fragment<wmma::matrix_a, 16, 16, 16, __half, wmma::row_major> af0, af1;
    wmma::fragment<wmma::matrix_b, 16, 16, 16, __half, wmma::col_major> bf;

    int nsc = (K + 255) >> 8;
    {
        int ke0 = (K < 256) ? K : 256;
        stage_chunk(smb + ABUF0, 0, ke0, s0, ld0, Kx, s1, m0);
        cp_async_commit();
    }
    for (int sc = 0; sc < nsc; ++sc) {
        int kb = sc << 8;
        int ke = kb + 256;
        if (ke > K) ke = K;
        if (sc + 1 < nsc) {
            int kb2 = (sc + 1) << 8;
            int ke2 = kb2 + 256;
            if (ke2 > K) ke2 = K;
            stage_chunk(smb + ABUF0 + (uint32_t)(((sc + 1) & 1) * ABSZ),
                        kb2, ke2, s0, ld0, Kx, s1, m0);
            cp_async_commit();
            cp_async_wait1();
        } else {
            cp_async_wait0();
        }
        __syncthreads();
        const __half* abase = (const __half*)(smraw + ABUF0 + (size_t)((sc & 1) * ABSZ))
                            + (size_t)(mi * 32) * ASTRH;
        const __half* bbase = (const __half*)smraw + (size_t)(ni * 16) * WSTRH + kb;
        int nslab = (ke - kb) >> 4;
#pragma unroll 4
        for (int sl = 0; sl < nslab; ++sl) {
            int kk = sl << 4;
            wmma::load_matrix_sync(af0, abase + kk, ASTRH);
            wmma::load_matrix_sync(af1, abase + 16 * ASTRH + kk, ASTRH);
            wmma::load_matrix_sync(bf, bbase + kk, WSTRH);
            wmma::mma_sync(acc0, af0, bf, acc0);
            wmma::mma_sync(acc1, af1, bf, acc1);
        }
        __syncthreads();
    }

    float* smf = (float*)(smraw + SMFOFF);
    wmma::store_matrix_sync(smf + (size_t)(mi * 32) * 64 + ni * 16, acc0, 64,
                            wmma::mem_row_major);
    wmma::store_matrix_sync(smf + (size_t)(mi * 32 + 16) * 64 + ni * 16, acc1, 64,
                            wmma::mem_row_major);
    __syncthreads();

#pragma unroll
    for (int j = 0; j < 4; ++j) {
        int m = mb + 16 * j;
        float4 gq = *(const float4*)(smf + (size_t)m * 64 + uloc * 4);
        float vi = gq.x + badd[j * 4 + 0];
        float vf = gq.y + badd[j * 4 + 1];
        float vg = gq.z + badd[j * 4 + 2];
        float vo = gq.w + badd[j * 4 + 3];
        float cn = sigf(vf) * cst[j] + sigf(vi) * tanhf(vg);
        float h  = sigf(vo) * tanhf(cn);
        cst[j] = cn;
        __half hh = __float2half(h);
        size_t off = (size_t)(m0 + m) * HID + u0 + uloc;
        hout[off] = hh;
        if (hsave) hsave[off] = hh;
    }
}

// ---------------- persistent wavefront kernel (dataflow-flag synced) ----------------
__global__ __launch_bounds__(256, 1) void lstm_hmma() {
    extern __shared__ char smraw[];
    uint32_t smb = smem_to_u32(smraw);
    int tid = threadIdx.x;
    int w = tid >> 5;
    int cta = blockIdx.x;
    int lb = cta & 63;
    bool top = (cta >= 64);
    int mh = lb >> 5;               // batch-half group
    int m0 = mh * 64;
    int u0 = (lb & 31) * 16;
    int mi = w >> 2;
    int ni = w & 3;
    int uloc = tid & 15;
    int mb = tid >> 4;              // epilogue base row (0..15)

    float badd[16];
    float cst[4];

    // ===== encoder =====
    if (!top) load_wsm(smraw, g_eWih0, INP, g_eWhh0, u0);
    else      load_wsm(smraw, g_eWih1, HID, g_eWhh1, u0);
    {
        const float* bias = top ? g_be1 : g_be0;
#pragma unroll
        for (int j = 0; j < 4; ++j)
#pragma unroll
            for (int g = 0; g < 4; ++g)
                badd[j * 4 + g] = bias[g * 512 + u0 + uloc];
    }
#pragma unroll
    for (int j = 0; j < 4; ++j) cst[j] = 0.f;
    __syncthreads();

    unsigned* fb = &g_flag[0 + mh];   // encoder bottom group counter
    unsigned* ft = &g_flag[2 + mh];   // encoder top group counter

    if (!top) {
        for (int t = 0; t < TT; ++t) {
            // need: own group done t-1 steps of reads; top done step t-2 (buffer anti-dep)
            wait2(fb, 32u * (unsigned)t,
                  ft, (t >= 2) ? 32u * (unsigned)(t - 1) : 0u);
            cell_step(smraw, smb, g_x16 + (size_t)t * BSZ * INP, INP, INP,
                      g_h0[(t + 1) & 1], INP + HID, badd, cst,
                      g_h0[t & 1], (__half*)0, m0, u0, mi, ni, uloc, mb);
            post_flag(fb);
        }
    } else {
        for (int t = 0; t < TT; ++t) {
            // need: bottom done step t; own group done step t-1
            wait2(fb, 32u * (unsigned)(t + 1),
                  ft, 32u * (unsigned)t);
            cell_step(smraw, smb, g_h0[t & 1], HID, HID,
                      g_h1[(t + 1) & 1], 2 * HID, badd, cst,
                      g_h1[t & 1], (__half*)0, m0, u0, mi, ni, uloc, mb);
            post_flag(ft);
        }
    }

    grid_sync(NCTA);

    // ===== gx = z @ dWih0^T (one-off; z = encoder h1 at t=127, parity 1) =====
    {
        wmma::fragment<wmma::accumulator, 16, 16, 16, float> acc1;
        wmma::fill_fragment(acc1, 0.f);
        wmma::fragment<wmma::matrix_a, 16, 16, 16, __half, wmma::row_major> af;
        wmma::fragment<wmma::matrix_b, 16, 16, 16, __half, wmma::col_major> bfx;
        const __half* ap = g_h1[1] + (size_t)(w * 16) * HID;
        const __half* bp = g_dWih0 + (size_t)(cta * 16) * HID;
#pragma unroll 4
        for (int k0 = 0; k0 < HID; k0 += 16) {
            wmma::load_matrix_sync(af, ap + k0, HID);
            wmma::load_matrix_sync(bfx, bp + k0, HID);
            wmma::mma_sync(acc1, af, bfx, acc1);
        }
        wmma::store_matrix_sync(g_gx + (size_t)(w * 16) * G4 + cta * 16, acc1,
                                G4, wmma::mem_row_major);
    }
    grid_sync(2 * NCTA);

    // ===== decoder =====
    if (!top) {
        load_wsm(smraw, (const __half*)0, 0, g_dWhh0, u0);
#pragma unroll
        for (int j = 0; j < 4; ++j)
#pragma unroll
            for (int g = 0; g < 4; ++g) {
                int colg = g * 512 + u0 + uloc;
                badd[j * 4 + g] = g_bd0[colg]
                                + g_gx[(size_t)(m0 + mb + 16 * j) * G4 + colg];
            }
    } else {
        load_wsm(smraw, g_dWih1, HID, g_dWhh1, u0);
#pragma unroll
        for (int j = 0; j < 4; ++j)
#pragma unroll
            for (int g = 0; g < 4; ++g)
                badd[j * 4 + g] = g_bd1[g * 512 + u0 + uloc];
    }
#pragma unroll
    for (int j = 0; j < 4; ++j) cst[j] = 0.f;
    __syncthreads();

    unsigned* fbd = &g_flag[4 + mh];
    unsigned* ftd = &g_flag[6 + mh];

    if (!top) {
        for (int t = 0; t < TT; ++t) {
            wait2(fbd, 32u * (unsigned)t,
                  ftd, (t >= 2) ? 32u * (unsigned)(t - 1) : 0u);
            cell_step(smraw, smb, (const __half*)0, 0, 0,
                      g_hd0[(t + 1) & 1], HID, badd, cst,
                      g_hd0[t & 1], (__half*)0, m0, u0, mi, ni, uloc, mb);
            post_flag(fbd);
        }
    } else {
        for (int t = 0; t < TT; ++t) {
            wait2(fbd, 32u * (unsigned)(t + 1),
                  ftd, 32u * (unsigned)t);
            cell_step(smraw, smb, g_hd0[t & 1], HID, HID,
                      g_hd1[(t + 1) & 1], 2 * HID, badd, cst,
                      g_hd1[t & 1], g_hs + (size_t)t * BSZ * HID,
                      m0, u0, mi, ni, uloc, mb);
            post_flag(ftd);
        }
    }
}

// ---------------- FC head ----------------
__global__ __launch_bounds__(128) void fc_kernel(const float* __restrict__ fcb,
                                                 float* __restrict__ out) {
    int m0 = blockIdx.x * 64;
    int w = threadIdx.x >> 5;

    wmma::fragment<wmma::accumulator, 16, 16, 16, float> acc[4];
#pragma unroll
    for (int mt = 0; mt < 4; mt++) wmma::fill_fragment(acc[mt], 0.f);
    wmma::fragment<wmma::matrix_a, 16, 16, 16, __half, wmma::row_major> af;
    wmma::fragment<wmma::matrix_b, 16, 16, 16, __half, wmma::col_major> bf;

    const __half* Wb = g_fcW + (size_t)(w * 16) * HID;
    for (int k0 = 0; k0 < HID; k0 += 16) {
        wmma::load_matrix_sync(bf, Wb + k0, HID);
#pragma unroll
        for (int mt = 0; mt < 4; mt++) {
            wmma::load_matrix_sync(af, g_hs + (size_t)(m0 + mt * 16) * HID + k0, HID);
            wmma::mma_sync(acc[mt], af, bf, acc[mt]);
        }
    }

    __shared__ float sm[64][64];
#pragma unroll
    for (int mt = 0; mt < 4; mt++) {
        wmma::store_matrix_sync(&sm[mt * 16][w * 16], acc[mt], 64, wmma::mem_row_major);
    }
    __syncthreads();

    for (int idx = threadIdx.x; idx < 4096; idx += 128) {
        int m = idx >> 6;
        int i = idx & 63;
        int gm = m0 + m;
        int b = gm & (BSZ - 1);
        int t = gm >> 7;
        out[(size_t)b * TT * INP + (size_t)t * INP + i] = sm[m][i] + fcb[i];
    }
}

// ---------------- launch ----------------
extern "C" void kernel_launch(void* const* d_in, const int* in_sizes, int n_in,
                              void* d_out, int out_size) {
    (void)in_sizes; (void)n_in; (void)out_size;
    const float* x      = (const float*)d_in[0];
    const float* eWih0  = (const float*)d_in[1];
    const float* eWhh0  = (const float*)d_in[2];
    const float* ebih0  = (const float*)d_in[3];
    const float* ebhh0  = (const float*)d_in[4];
    const float* eWih1  = (const float*)d_in[5];
    const float* eWhh1  = (const float*)d_in[6];
    const float* ebih1  = (const float*)d_in[7];
    const float* ebhh1  = (const float*)d_in[8];
    const float* dWih0  = (const float*)d_in[9];
    const float* dWhh0  = (const float*)d_in[10];
    const float* dbih0  = (const float*)d_in[11];
    const float* dbhh0  = (const float*)d_in[12];
    const float* dWih1  = (const float*)d_in[13];
    const float* dWhh1  = (const float*)d_in[14];
    const float* dbih1  = (const float*)d_in[15];
    const float* dbhh1  = (const float*)d_in[16];
    const float* fcW    = (const float*)d_in[17];
    const float* fcb    = (const float*)d_in[18];
    float* out = (float*)d_out;

    cudaFuncSetAttribute(lstm_hmma,
                         cudaFuncAttributeMaxDynamicSharedMemorySize, SMEM_TOTAL);

    prep_kernel<<<2048, 256>>>(x, eWih0, eWhh0, ebih0, ebhh0,
                               eWih1, eWhh1, ebih1, ebhh1,
                               dWih0, dWhh0, dbih0, dbhh0,
                               dWih1, dWhh1, dbih1, dbhh1, fcW);

    lstm_hmma<<<NCTA, 256, SMEM_TOTAL>>>();

    fc_kernel<<<256, 128>>>(fcb, out);
}

// round 10
// speedup vs baseline: 1.0120x; 1.0120x over previous
#include <cstdint>
#include <cstddef>
#include <cuda_runtime.h>
#include <cuda_fp16.h>
#include <mma.h>

using namespace nvcuda;

#define BSZ 128
#define TT  128
#define INP 64
#define HID 512
#define G4  2048
#define HB  (BSZ*HID)
#define NCTA 128

// dynamic smem map (bytes):
//   [0, 132096)          weights: 64 rows x 1032 halves (stride 2064 B)
//   [132096, 184320)     A ring: 3 chunk buffers x 17408 B (64 rows x 136 halves)
//   [184320, 217088)     smf: 2 (k-groups) x 64x64 float
#define WSTRH   1032
#define WSTRB   2064
#define ASTRH   136
#define ASTRB   272
#define ABUF0   132096
#define ABSZ    17408
#define SMFOFF  184320
#define SMEM_TOTAL 217088

// ---------------- device state ----------------
__device__ __align__(128) __half g_eWih0[G4*INP];
__device__ __align__(128) __half g_eWhh0[G4*HID];
__device__ __align__(128) __half g_eWih1[G4*HID];
__device__ __align__(128) __half g_eWhh1[G4*HID];
__device__ __align__(128) __half g_dWih0[G4*HID];
__device__ __align__(128) __half g_dWhh0[G4*HID];
__device__ __align__(128) __half g_dWih1[G4*HID];
__device__ __align__(128) __half g_dWhh1[G4*HID];
__device__ __align__(128) __half g_fcW[INP*HID];
__device__ float  g_be0[G4];
__device__ float  g_be1[G4];
__device__ float  g_bd0[G4];
__device__ float  g_bd1[G4];
__device__ __align__(128) __half g_x16[TT*BSZ*INP];
__device__ __align__(128) __half g_h0[2][HB];
__device__ __align__(128) __half g_h1[2][HB];
__device__ __align__(128) __half g_hd0[2][HB];
__device__ __align__(128) __half g_hd1[2][HB];
__device__ float  g_gx[BSZ*G4];
__device__ __align__(128) __half g_hs[TT*BSZ*HID];
__device__ unsigned g_ctr;
__device__ unsigned g_flag[8];   // [enc bot0,bot1,top0,top1][dec bot0,bot1,top0,top1]

// ---------------- prep ----------------
__global__ void prep_kernel(
    const float* __restrict__ x,
    const float* __restrict__ eWih0, const float* __restrict__ eWhh0,
    const float* __restrict__ ebih0, const float* __restrict__ ebhh0,
    const float* __restrict__ eWih1, const float* __restrict__ eWhh1,
    const float* __restrict__ ebih1, const float* __restrict__ ebhh1,
    const float* __restrict__ dWih0, const float* __restrict__ dWhh0,
    const float* __restrict__ dbih0, const float* __restrict__ dbhh0,
    const float* __restrict__ dWih1, const float* __restrict__ dWhh1,
    const float* __restrict__ dbih1, const float* __restrict__ dbhh1,
    const float* __restrict__ fcW)
{
    const long NP = 8822793;
    long stride = (long)gridDim.x * blockDim.x;
    for (long i = (long)blockIdx.x * blockDim.x + threadIdx.x; i < NP; i += stride) {
        long r = i;
        if (r < 131072)  { g_eWih0[r] = __float2half(eWih0[r]); continue; } r -= 131072;
        if (r < 1048576) { g_eWhh0[r] = __float2half(eWhh0[r]); continue; } r -= 1048576;
        if (r < 1048576) { g_eWih1[r] = __float2half(eWih1[r]); continue; } r -= 1048576;
        if (r < 1048576) { g_eWhh1[r] = __float2half(eWhh1[r]); continue; } r -= 1048576;
        if (r < 1048576) { g_dWih0[r] = __float2half(dWih0[r]); continue; } r -= 1048576;
        if (r < 1048576) { g_dWhh0[r] = __float2half(dWhh0[r]); continue; } r -= 1048576;
        if (r < 1048576) { g_dWih1[r] = __float2half(dWih1[r]); continue; } r -= 1048576;
        if (r < 1048576) { g_dWhh1[r] = __float2half(dWhh1[r]); continue; } r -= 1048576;
        if (r < 32768)   { g_fcW[r]   = __float2half(fcW[r]);   continue; } r -= 32768;
        if (r < 8192) {
            int which = (int)(r >> 11);
            int j = (int)(r & 2047);
            if      (which == 0) g_be0[j] = ebih0[j] + ebhh0[j];
            else if (which == 1) g_be1[j] = ebih1[j] + ebhh1[j];
            else if (which == 2) g_bd0[j] = dbih0[j] + dbhh0[j];
            else                 g_bd1[j] = dbih1[j] + dbhh1[j];
            continue;
        } r -= 8192;
        if (r < 1048576) {
            int t = (int)(r >> 13);
            int rem = (int)(r & 8191);
            int b = rem >> 6;
            int k = rem & 63;
            g_x16[r] = __float2half(x[(size_t)b * TT * INP + (size_t)t * INP + k]);
            continue;
        } r -= 1048576;
        if (r < 262144) {
            int which = (int)(r >> 16);
            int j = (int)(r & 65535);
            __half z = __float2half(0.f);
            if      (which == 0) g_h0[1][j]  = z;
            else if (which == 1) g_h1[1][j]  = z;
            else if (which == 2) g_hd0[1][j] = z;
            else                 g_hd1[1][j] = z;
            continue;
        } r -= 262144;
        {   // 9 sync words per replay
            if (r < 8) g_flag[r] = 0u;
            else       g_ctr = 0u;
        }
    }
}

// ---------------- helpers ----------------
__device__ __forceinline__ void cp_async16(uint32_t dst_smem, const void* src) {
    asm volatile("cp.async.cg.shared.global [%0], [%1], 16;"
                 :: "r"(dst_smem), "l"(src) : "memory");
}
__device__ __forceinline__ void cp_async_commit() {
    asm volatile("cp.async.commit_group;" ::: "memory");
}
__device__ __forceinline__ void cp_async_wait0() {
    asm volatile("cp.async.wait_group 0;" ::: "memory");
}
__device__ __forceinline__ void cp_async_wait1() {
    asm volatile("cp.async.wait_group 1;" ::: "memory");
}
__device__ __forceinline__ uint32_t smem_to_u32(const void* smem_ptr) {
    uint32_t addr;
    asm("{ .reg .u64 tmp; cvta.to.shared.u64 tmp, %1; cvt.u32.u64 %0, tmp; }"
        : "=r"(addr) : "l"(smem_ptr));
    return addr;
}
__device__ __forceinline__ float sigf(float v) { return 1.f / (1.f + __expf(-v)); }

// ---------------- sync primitives ----------------
__device__ __forceinline__ void grid_sync(unsigned target) {
    __syncthreads();
    if (threadIdx.x == 0) {
        __threadfence();
        atomicAdd(&g_ctr, 1u);
        volatile unsigned* cp = &g_ctr;
        while (*cp < target) { }
        __threadfence();
    }
    __syncthreads();
}
// spin (tid0) until *f >= v, then block-wide release
__device__ __forceinline__ void waitflag(unsigned* f, unsigned v) {
    if (threadIdx.x == 0) {
        volatile unsigned* p = f;
        while (*p < v) { }
        __threadfence();
    }
    __syncthreads();
}
__device__ __forceinline__ void post_flag(unsigned* f) {
    __syncthreads();
    if (threadIdx.x == 0) {
        __threadfence();
        atomicAdd(f, 1u);
    }
}

// ---------------- stationary weight load ----------------
// smem row c (D-col c): weight row grow = (c&3)*512 + u0 + (c>>2); row = [W1 | W2]
__device__ void load_wsm(char* smraw, const __half* __restrict__ W1, int Kx,
                         const __half* __restrict__ W2, int u0) {
    int K = Kx + 512;
    int ng = K >> 3;
    int tot = 64 * ng;
    for (int idx = threadIdx.x; idx < tot; idx += 256) {
        int c = idx / ng;
        int gi = idx - c * ng;
        int k = gi << 3;
        int grow = (c & 3) * 512 + u0 + (c >> 2);
        uint4 v;
        if (k < Kx) v = *(const uint4*)(W1 + (size_t)grow * Kx + k);
        else        v = *(const uint4*)(W2 + (size_t)grow * 512 + (k - Kx));
        *(uint4*)(smraw + (size_t)c * WSTRB + ((size_t)k << 1)) = v;
    }
}

// ---------------- stage one A chunk [64 rows x (ke-kb) halves], ke-kb in {128,64} ----------------
__device__ __forceinline__ void stage_chunk(uint32_t dst, int kb, int ke,
                                            const __half* __restrict__ s0, int ld0, int Kx,
                                            const __half* __restrict__ s1, int m0) {
    int cols = ke - kb;
    if (cols == 128) {
#pragma unroll
        for (int i = 0; i < 4; i++) {
            int idx = (int)threadIdx.x + i * 256;
            int r = idx >> 4;
            int gi = idx & 15;
            int k = kb + (gi << 3);
            const __half* src;
            if (k < Kx) src = s0 + (size_t)(m0 + r) * ld0 + k;
            else        src = s1 + (size_t)(m0 + r) * HID + (k - Kx);
            cp_async16(dst + (uint32_t)(r * ASTRB + (gi << 4)), src);
        }
    } else {   // 64 cols
#pragma unroll
        for (int i = 0; i < 2; i++) {
            int idx = (int)threadIdx.x + i * 256;
            int r = idx >> 3;
            int gi = idx & 7;
            int k = kb + (gi << 3);
            const __half* src;
            if (k < Kx) src = s0 + (size_t)(m0 + r) * ld0 + k;
            else        src = s1 + (size_t)(m0 + r) * HID + (k - Kx);
            cp_async16(dst + (uint32_t)(r * ASTRB + (gi << 4)), src);
        }
    }
}

// ---------------- one LSTM cell step ----------------
// CTA tile: 64 batch x 64 gate-cols (16 units x 4 gates, gate = col&3)
// 8 warps = kg(2) x mi(2) x ni(2): 32x32 warp tiles, 2-way k-split within each chunk.
__device__ __forceinline__ void cell_step(
    char* smraw, uint32_t smb,
    const __half* __restrict__ s0, int ld0, int Kx,
    const __half* __restrict__ s1, int K,
    const float* badd, float* cst,
    __half* __restrict__ hout, __half* __restrict__ hsave,
    int m0, int u0,
    int kg, int mi, int ni, int uloc, int mb,
    unsigned* wB, unsigned vB,           // JIT wait before staging chunk 4 (null = none)
    unsigned* wE, unsigned vE)           // anti-dep wait before epilogue stores (null = none)
{
    wmma::fragment<wmma::accumulator, 16, 16, 16, float> a00, a01, a10, a11;
    wmma::fill_fragment(a00, 0.f);
    wmma::fill_fragment(a01, 0.f);
    wmma::fill_fragment(a10, 0.f);
    wmma::fill_fragment(a11, 0.f);
    wmma::fragment<wmma::matrix_a, 16, 16, 16, __half, wmma::row_major> af0, af1;
    wmma::fragment<wmma::matrix_b, 16, 16, 16, __half, wmma::col_major> bf0, bf1;

    int nch = (K + 127) >> 7;
    // prologue: stage chunks 0 and 1
    {
        int ke0 = (K < 128) ? K : 128;
        stage_chunk(smb + ABUF0, 0, ke0, s0, ld0, Kx, s1, m0);
        cp_async_commit();
        int ke1 = (K < 256) ? K : 256;
        stage_chunk(smb + ABUF0 + ABSZ, 128, ke1, s0, ld0, Kx, s1, m0);
        cp_async_commit();
    }
    int buf = 0;       // buffer of chunk i
    for (int i = 0; i < nch; ++i) {
        if (wB && i == 2) waitflag(wB, vB);
        if (i + 1 < nch) cp_async_wait1(); else cp_async_wait0();
        __syncthreads();
        if (i + 2 < nch) {
            int kb2 = (i + 2) << 7;
            int ke2 = kb2 + 128;
            if (ke2 > K) ke2 = K;
            int buf2 = buf + 2;
            if (buf2 >= 3) buf2 -= 3;
            stage_chunk(smb + ABUF0 + (uint32_t)buf2 * ABSZ, kb2, ke2, s0, ld0, Kx, s1, m0);
            cp_async_commit();
        }
        int kb = i << 7;
        int ke = kb + 128;
        if (ke > K) ke = K;
        const __half* abase = (const __half*)(smraw + ABUF0 + (size_t)buf * ABSZ)
                            + (size_t)(mi * 32) * ASTRH;
        const __half* bbase = (const __half*)smraw + (size_t)(ni * 32) * WSTRH + kb;
        int half = (ke - kb) >> 5;     // slabs per k-group: 4 (128 cols) or 2 (64 cols)
#pragma unroll 4
        for (int s = 0; s < half; ++s) {
            int kk = (kg * half + s) << 4;
            wmma::load_matrix_sync(af0, abase + kk, ASTRH);
            wmma::load_matrix_sync(af1, abase + 16 * ASTRH + kk, ASTRH);
            wmma::load_matrix_sync(bf0, bbase + kk, WSTRH);
            wmma::load_matrix_sync(bf1, bbase + 16 * WSTRH + kk, WSTRH);
            wmma::mma_sync(a00, af0, bf0, a00);
            wmma::mma_sync(a01, af0, bf1, a01);
            wmma::mma_sync(a10, af1, bf0, a10);
            wmma::mma_sync(a11, af1, bf1, a11);
        }
        buf = buf + 1;
        if (buf >= 3) buf = 0;
    }

    // k-group partials -> smf, reduce in epilogue
    float* smf = (float*)(smraw + SMFOFF) + (size_t)kg * 4096;
    wmma::store_matrix_sync(smf + (size_t)(mi * 32) * 64 + ni * 32,           a00, 64, wmma::mem_row_major);
    wmma::store_matrix_sync(smf + (size_t)(mi * 32) * 64 + ni * 32 + 16,      a01, 64, wmma::mem_row_major);
    wmma::store_matrix_sync(smf + (size_t)(mi * 32 + 16) * 64 + ni * 32,      a10, 64, wmma::mem_row_major);
    wmma::store_matrix_sync(smf + (size_t)(mi * 32 + 16) * 64 + ni * 32 + 16, a11, 64, wmma::mem_row_major);
    __syncthreads();
    if (wE) waitflag(wE, vE);

    const float* smf0 = (const float*)(smraw + SMFOFF);
    const float* smf1 = smf0 + 4096;
#pragma unroll
    for (int j = 0; j < 4; ++j) {
        int m = mb + 16 * j;
        float4 q0 = *(const float4*)(smf0 + (size_t)m * 64 + uloc * 4);
        float4 q1 = *(const float4*)(smf1 + (size_t)m * 64 + uloc * 4);
        float vi = q0.x + q1.x + badd[j * 4 + 0];
        float vf = q0.y + q1.y + badd[j * 4 + 1];
        float vg = q0.z + q1.z + badd[j * 4 + 2];
        float vo = q0.w + q1.w + badd[j * 4 + 3];
        float cn = sigf(vf) * cst[j] + sigf(vi) * tanhf(vg);
        float h  = sigf(vo) * tanhf(cn);
        cst[j] = cn;
        __half hh = __float2half(h);
        size_t off = (size_t)(m0 + m) * HID + u0 + uloc;
        hout[off] = hh;
        if (hsave) hsave[off] = hh;
    }
}

// ---------------- persistent wavefront kernel ----------------
__global__ __launch_bounds__(256, 1) void lstm_hmma() {
    extern __shared__ char smraw[];
    uint32_t smb = smem_to_u32(smraw);
    int tid = threadIdx.x;
    int w = tid >> 5;
    int cta = blockIdx.x;
    int lb = cta & 63;
    bool top = (cta >= 64);
    int mh = lb >> 5;
    int m0 = mh * 64;
    int u0 = (lb & 31) * 16;
    int kg = w & 1;
    int mi = (w >> 1) & 1;
    int ni = w >> 2;
    int uloc = tid & 15;
    int mb = tid >> 4;

    float badd[16];
    float cst[4];

    // ===== encoder =====
    if (!top) load_wsm(smraw, g_eWih0, INP, g_eWhh0, u0);
    else      load_wsm(smraw, g_eWih1, HID, g_eWhh1, u0);
    {
        const float* bias = top ? g_be1 : g_be0;
#pragma unroll
        for (int j = 0; j < 4; ++j)
#pragma unroll
            for (int g = 0; g < 4; ++g)
                badd[j * 4 + g] = bias[g * 512 + u0 + uloc];
    }
#pragma unroll
    for (int j = 0; j < 4; ++j) cst[j] = 0.f;
    __syncthreads();

    unsigned* fb = &g_flag[0 + mh];
    unsigned* ft = &g_flag[2 + mh];

    if (!top) {
        for (int t = 0; t < TT; ++t) {
            waitflag(fb, 32u * (unsigned)t);
            cell_step(smraw, smb, g_x16 + (size_t)t * BSZ * INP, INP, INP,
                      g_h0[(t + 1) & 1], INP + HID, badd, cst,
                      g_h0[t & 1], (__half*)0, m0, u0, kg, mi, ni, uloc, mb,
                      (unsigned*)0, 0u,
                      (t >= 2) ? ft : (unsigned*)0, 32u * (unsigned)(t - 1));
            post_flag(fb);
        }
    } else {
        for (int t = 0; t < TT; ++t) {
            waitflag(fb, 32u * (unsigned)(t + 1));
            cell_step(smraw, smb, g_h0[t & 1], HID, HID,
                      g_h1[(t + 1) & 1], 2 * HID, badd, cst,
                      g_h1[t & 1], (__half*)0, m0, u0, kg, mi, ni, uloc, mb,
                      ft, 32u * (unsigned)t,
                      (unsigned*)0, 0u);
            post_flag(ft);
        }
    }

    grid_sync(NCTA);

    // ===== gx = z @ dWih0^T (one-off; z = encoder h1 at t=127, parity 1) =====
    {
        wmma::fragment<wmma::accumulator, 16, 16, 16, float> acc1;
        wmma::fill_fragment(acc1, 0.f);
        wmma::fragment<wmma::matrix_a, 16, 16, 16, __half, wmma::row_major> af;
        wmma::fragment<wmma::matrix_b, 16, 16, 16, __half, wmma::col_major> bfx;
        const __half* ap = g_h1[1] + (size_t)(w * 16) * HID;
        const __half* bp = g_dWih0 + (size_t)(cta * 16) * HID;
#pragma unroll 4
        for (int k0 = 0; k0 < HID; k0 += 16) {
            wmma::load_matrix_sync(af, ap + k0, HID);
            wmma::load_matrix_sync(bfx, bp + k0, HID);
            wmma::mma_sync(acc1, af, bfx, acc1);
        }
        wmma::store_matrix_sync(g_gx + (size_t)(w * 16) * G4 + cta * 16, acc1,
                                G4, wmma::mem_row_major);
    }
    grid_sync(2 * NCTA);

    // ===== decoder =====
    if (!top) {
        load_wsm(smraw, (const __half*)0, 0, g_dWhh0, u0);
#pragma unroll
        for (int j = 0; j < 4; ++j)
#pragma unroll
            for (int g = 0; g < 4; ++g) {
                int colg = g * 512 + u0 + uloc;
                badd[j * 4 + g] = g_bd0[colg]
                                + g_gx[(size_t)(m0 + mb + 16 * j) * G4 + colg];
            }
    } else {
        load_wsm(smraw, g_dWih1, HID, g_dWhh1, u0);
#pragma unroll
        for (int j = 0; j < 4; ++j)
#pragma unroll
            for (int g = 0; g < 4; ++g)
                badd[j * 4 + g] = g_bd1[g * 512 + u0 + uloc];
    }
#pragma unroll
    for (int j = 0; j < 4; ++j) cst[j] = 0.f;
    __syncthreads();

    unsigned* fbd = &g_flag[4 + mh];
    unsigned* ftd = &g_flag[6 + mh];

    if (!top) {
        for (int t = 0; t < TT; ++t) {
            waitflag(fbd, 32u * (unsigned)t);
            cell_step(smraw, smb, (const __half*)0, 0, 0,
                      g_hd0[(t + 1) & 1], HID, badd, cst,
                      g_hd0[t & 1], (__half*)0, m0, u0, kg, mi, ni, uloc, mb,
                      (unsigned*)0, 0u,
                      (t >= 2) ? ftd : (unsigned*)0, 32u * (unsigned)(t - 1));
            post_flag(fbd);
        }
    } else {
        for (int t = 0; t < TT; ++t) {
            waitflag(fbd, 32u * (unsigned)(t + 1));
            cell_step(smraw, smb, g_hd0[t & 1], HID, HID,
                      g_hd1[(t + 1) & 1], 2 * HID, badd, cst,
                      g_hd1[t & 1], g_hs + (size_t)t * BSZ * HID,
                      m0, u0, kg, mi, ni, uloc, mb,
                      ftd, 32u * (unsigned)t,
                      (unsigned*)0, 0u);
            post_flag(ftd);
        }
    }
}

// ---------------- FC head ----------------
__global__ __launch_bounds__(128) void fc_kernel(const float* __restrict__ fcb,
                                                 float* __restrict__ out) {
    int m0 = blockIdx.x * 64;
    int w = threadIdx.x >> 5;

    wmma::fragment<wmma::accumulator, 16, 16, 16, float> acc[4];
#pragma unroll
    for (int mt = 0; mt < 4; mt++) wmma::fill_fragment(acc[mt], 0.f);
    wmma::fragment<wmma::matrix_a, 16, 16, 16, __half, wmma::row_major> af;
    wmma::fragment<wmma::matrix_b, 16, 16, 16, __half, wmma::col_major> bf;

    const __half* Wb = g_fcW + (size_t)(w * 16) * HID;
    for (int k0 = 0; k0 < HID; k0 += 16) {
        wmma::load_matrix_sync(bf, Wb + k0, HID);
#pragma unroll
        for (int mt = 0; mt < 4; mt++) {
            wmma::load_matrix_sync(af, g_hs + (size_t)(m0 + mt * 16) * HID + k0, HID);
            wmma::mma_sync(acc[mt], af, bf, acc[mt]);
        }
    }

    __shared__ float sm[64][64];
#pragma unroll
    for (int mt = 0; mt < 4; mt++) {
        wmma::store_matrix_sync(&sm[mt * 16][w * 16], acc[mt], 64, wmma::mem_row_major);
    }
    __syncthreads();

    for (int idx = threadIdx.x; idx < 4096; idx += 128) {
        int m = idx >> 6;
        int i = idx & 63;
        int gm = m0 + m;
        int b = gm & (BSZ - 1);
        int t = gm >> 7;
        out[(size_t)b * TT * INP + (size_t)t * INP + i] = sm[m][i] + fcb[i];
    }
}

// ---------------- launch ----------------
extern "C" void kernel_launch(void* const* d_in, const int* in_sizes, int n_in,
                              void* d_out, int out_size) {
    (void)in_sizes; (void)n_in; (void)out_size;
    const float* x      = (const float*)d_in[0];
    const float* eWih0  = (const float*)d_in[1];
    const float* eWhh0  = (const float*)d_in[2];
    const float* ebih0  = (const float*)d_in[3];
    const float* ebhh0  = (const float*)d_in[4];
    const float* eWih1  = (const float*)d_in[5];
    const float* eWhh1  = (const float*)d_in[6];
    const float* ebih1  = (const float*)d_in[7];
    const float* ebhh1  = (const float*)d_in[8];
    const float* dWih0  = (const float*)d_in[9];
    const float* dWhh0  = (const float*)d_in[10];
    const float* dbih0  = (const float*)d_in[11];
    const float* dbhh0  = (const float*)d_in[12];
    const float* dWih1  = (const float*)d_in[13];
    const float* dWhh1  = (const float*)d_in[14];
    const float* dbih1  = (const float*)d_in[15];
    const float* dbhh1  = (const float*)d_in[16];
    const float* fcW    = (const float*)d_in[17];
    const float* fcb    = (const float*)d_in[18];
    float* out = (float*)d_out;

    cudaFuncSetAttribute(lstm_hmma,
                         cudaFuncAttributeMaxDynamicSharedMemorySize, SMEM_TOTAL);

    prep_kernel<<<2048, 256>>>(x, eWih0, eWhh0, ebih0, ebhh0,
                               eWih1, eWhh1, ebih1, ebhh1,
                               dWih0, dWhh0, dbih0, dbhh0,
                               dWih1, dWhh1, dbih1, dbhh1, fcW);

    lstm_hmma<<<NCTA, 256, SMEM_TOTAL>>>();

    fc_kernel<<<256, 128>>>(fcb, out);
}

// round 11
// speedup vs baseline: 1.0138x; 1.0018x over previous
#include <cstdint>
#include <cstddef>
#include <cuda_runtime.h>
#include <cuda_fp16.h>
#include <mma.h>

using namespace nvcuda;

#define BSZ 128
#define TT  128
#define INP 64
#define HID 512
#define G4  2048
#define HB  (BSZ*HID)
#define NCTA 128

// dynamic smem map (bytes):
//   [0, 132096)          weights: 64 rows x 1032 halves (stride 2064 B)
//   [132096, 184320)     A ring: 3 chunk buffers x 17408 B (64 rows x 136 halves)
//   [184320, 217088)     smf: 2 (k-groups) x 64x64 float
#define WSTRH   1032
#define WSTRB   2064
#define ASTRH   136
#define ASTRB   272
#define ABUF0   132096
#define ABSZ    17408
#define SMFOFF  184320
#define SMEM_TOTAL 217088

// ---------------- device state ----------------
__device__ __align__(128) __half g_eWih0[G4*INP];
__device__ __align__(128) __half g_eWhh0[G4*HID];
__device__ __align__(128) __half g_eWih1[G4*HID];
__device__ __align__(128) __half g_eWhh1[G4*HID];
__device__ __align__(128) __half g_dWih0[G4*HID];
__device__ __align__(128) __half g_dWhh0[G4*HID];
__device__ __align__(128) __half g_dWih1[G4*HID];
__device__ __align__(128) __half g_dWhh1[G4*HID];
__device__ __align__(128) __half g_fcW[INP*HID];
__device__ float  g_be0[G4];
__device__ float  g_be1[G4];
__device__ float  g_bd0[G4];
__device__ float  g_bd1[G4];
__device__ __align__(128) __half g_x16[TT*BSZ*INP];
__device__ __align__(128) __half g_h0[2][HB];
__device__ __align__(128) __half g_h1[2][HB];
__device__ __align__(128) __half g_hd0[2][HB];
__device__ __align__(128) __half g_hd1[2][HB];
__device__ float  g_gx[BSZ*G4];
__device__ __align__(128) __half g_hs[TT*BSZ*HID];
__device__ unsigned g_ctr;
__device__ unsigned g_flag[8];   // [enc bot0,bot1,top0,top1][dec bot0,bot1,top0,top1]

// ---------------- prep ----------------
__global__ void prep_kernel(
    const float* __restrict__ x,
    const float* __restrict__ eWih0, const float* __restrict__ eWhh0,
    const float* __restrict__ ebih0, const float* __restrict__ ebhh0,
    const float* __restrict__ eWih1, const float* __restrict__ eWhh1,
    const float* __restrict__ ebih1, const float* __restrict__ ebhh1,
    const float* __restrict__ dWih0, const float* __restrict__ dWhh0,
    const float* __restrict__ dbih0, const float* __restrict__ dbhh0,
    const float* __restrict__ dWih1, const float* __restrict__ dWhh1,
    const float* __restrict__ dbih1, const float* __restrict__ dbhh1,
    const float* __restrict__ fcW)
{
    const long NP = 8822793;
    long stride = (long)gridDim.x * blockDim.x;
    for (long i = (long)blockIdx.x * blockDim.x + threadIdx.x; i < NP; i += stride) {
        long r = i;
        if (r < 131072)  { g_eWih0[r] = __float2half(eWih0[r]); continue; } r -= 131072;
        if (r < 1048576) { g_eWhh0[r] = __float2half(eWhh0[r]); continue; } r -= 1048576;
        if (r < 1048576) { g_eWih1[r] = __float2half(eWih1[r]); continue; } r -= 1048576;
        if (r < 1048576) { g_eWhh1[r] = __float2half(eWhh1[r]); continue; } r -= 1048576;
        if (r < 1048576) { g_dWih0[r] = __float2half(dWih0[r]); continue; } r -= 1048576;
        if (r < 1048576) { g_dWhh0[r] = __float2half(dWhh0[r]); continue; } r -= 1048576;
        if (r < 1048576) { g_dWih1[r] = __float2half(dWih1[r]); continue; } r -= 1048576;
        if (r < 1048576) { g_dWhh1[r] = __float2half(dWhh1[r]); continue; } r -= 1048576;
        if (r < 32768)   { g_fcW[r]   = __float2half(fcW[r]);   continue; } r -= 32768;
        if (r < 8192) {
            int which = (int)(r >> 11);
            int j = (int)(r & 2047);
            if      (which == 0) g_be0[j] = ebih0[j] + ebhh0[j];
            else if (which == 1) g_be1[j] = ebih1[j] + ebhh1[j];
            else if (which == 2) g_bd0[j] = dbih0[j] + dbhh0[j];
            else                 g_bd1[j] = dbih1[j] + dbhh1[j];
            continue;
        } r -= 8192;
        if (r < 1048576) {
            int t = (int)(r >> 13);
            int rem = (int)(r & 8191);
            int b = rem >> 6;
            int k = rem & 63;
            g_x16[r] = __float2half(x[(size_t)b * TT * INP + (size_t)t * INP + k]);
            continue;
        } r -= 1048576;
        if (r < 262144) {
            int which = (int)(r >> 16);
            int j = (int)(r & 65535);
            __half z = __float2half(0.f);
            if      (which == 0) g_h0[1][j]  = z;
            else if (which == 1) g_h1[1][j]  = z;
            else if (which == 2) g_hd0[1][j] = z;
            else                 g_hd1[1][j] = z;
            continue;
        } r -= 262144;
        {   // 9 sync words per replay
            if (r < 8) g_flag[r] = 0u;
            else       g_ctr = 0u;
        }
    }
}

// ---------------- helpers ----------------
__device__ __forceinline__ void cp_async16(uint32_t dst_smem, const void* src) {
    asm volatile("cp.async.cg.shared.global [%0], [%1], 16;"
                 :: "r"(dst_smem), "l"(src) : "memory");
}
__device__ __forceinline__ void cp_async_commit() {
    asm volatile("cp.async.commit_group;" ::: "memory");
}
__device__ __forceinline__ void cp_async_wait0() {
    asm volatile("cp.async.wait_group 0;" ::: "memory");
}
__device__ __forceinline__ void cp_async_wait1() {
    asm volatile("cp.async.wait_group 1;" ::: "memory");
}
__device__ __forceinline__ uint32_t smem_to_u32(const void* smem_ptr) {
    uint32_t addr;
    asm("{ .reg .u64 tmp; cvta.to.shared.u64 tmp, %1; cvt.u32.u64 %0, tmp; }"
        : "=r"(addr) : "l"(smem_ptr));
    return addr;
}
__device__ __forceinline__ float sigf(float v) { return 1.f / (1.f + __expf(-v)); }

// ---------------- sync primitives ----------------
__device__ __forceinline__ void grid_sync(unsigned target) {
    __syncthreads();
    if (threadIdx.x == 0) {
        __threadfence();
        atomicAdd(&g_ctr, 1u);
        volatile unsigned* cp = &g_ctr;
        while (*cp < target) { }
        __threadfence();
    }
    __syncthreads();
}
// spin (tid0) until *f >= v, then block-wide release
__device__ __forceinline__ void waitflag(unsigned* f, unsigned v) {
    if (threadIdx.x == 0) {
        volatile unsigned* p = f;
        while (*p < v) { }
        __threadfence();
    }
    __syncthreads();
}
__device__ __forceinline__ void post_flag(unsigned* f) {
    __syncthreads();
    if (threadIdx.x == 0) {
        __threadfence();
        atomicAdd(f, 1u);
    }
}

// ---------------- stationary weight load ----------------
// smem row c (D-col c): weight row grow = (c&3)*512 + u0 + (c>>2); row = [W1 | W2]
__device__ void load_wsm(char* smraw, const __half* __restrict__ W1, int Kx,
                         const __half* __restrict__ W2, int u0) {
    int K = Kx + 512;
    int ng = K >> 3;
    int tot = 64 * ng;
    for (int idx = threadIdx.x; idx < tot; idx += 256) {
        int c = idx / ng;
        int gi = idx - c * ng;
        int k = gi << 3;
        int grow = (c & 3) * 512 + u0 + (c >> 2);
        uint4 v;
        if (k < Kx) v = *(const uint4*)(W1 + (size_t)grow * Kx + k);
        else        v = *(const uint4*)(W2 + (size_t)grow * 512 + (k - Kx));
        *(uint4*)(smraw + (size_t)c * WSTRB + ((size_t)k << 1)) = v;
    }
}

// ---------------- stage one A chunk [64 rows x (ke-kb) halves], ke-kb in {128,64} ----------------
__device__ __forceinline__ void stage_chunk(uint32_t dst, int kb, int ke,
                                            const __half* __restrict__ s0, int ld0, int Kx,
                                            const __half* __restrict__ s1, int m0) {
    int cols = ke - kb;
    if (cols == 128) {
#pragma unroll
        for (int i = 0; i < 4; i++) {
            int idx = (int)threadIdx.x + i * 256;
            int r = idx >> 4;
            int gi = idx & 15;
            int k = kb + (gi << 3);
            const __half* src;
            if (k < Kx) src = s0 + (size_t)(m0 + r) * ld0 + k;
            else        src = s1 + (size_t)(m0 + r) * HID + (k - Kx);
            cp_async16(dst + (uint32_t)(r * ASTRB + (gi << 4)), src);
        }
    } else {   // 64 cols
#pragma unroll
        for (int i = 0; i < 2; i++) {
            int idx = (int)threadIdx.x + i * 256;
            int r = idx >> 3;
            int gi = idx & 7;
            int k = kb + (gi << 3);
            const __half* src;
            if (k < Kx) src = s0 + (size_t)(m0 + r) * ld0 + k;
            else        src = s1 + (size_t)(m0 + r) * HID + (k - Kx);
            cp_async16(dst + (uint32_t)(r * ASTRB + (gi << 4)), src);
        }
    }
}

// ---------------- one LSTM cell step ----------------
// CTA tile: 64 batch x 64 gate-cols (16 units x 4 gates, gate = col&3)
// 8 warps = kg(2) x mi(2) x ni(2): 32x32 warp tiles, 2-way k-split within each chunk.
__device__ __forceinline__ void cell_step(
    char* smraw, uint32_t smb,
    const __half* __restrict__ s0, int ld0, int Kx,
    const __half* __restrict__ s1, int K,
    const float* badd, float* cst,
    __half* __restrict__ hout, __half* __restrict__ hsave,
    int m0, int u0,
    int kg, int mi, int ni, int uloc, int mb,
    unsigned* wB, unsigned vB,           // JIT wait before staging chunk 4 (null = none)
    unsigned* wE, unsigned vE)           // anti-dep wait before epilogue stores (null = none)
{
    wmma::fragment<wmma::accumulator, 16, 16, 16, float> a00, a01, a10, a11;
    wmma::fill_fragment(a00, 0.f);
    wmma::fill_fragment(a01, 0.f);
    wmma::fill_fragment(a10, 0.f);
    wmma::fill_fragment(a11, 0.f);
    wmma::fragment<wmma::matrix_a, 16, 16, 16, __half, wmma::row_major> af0, af1;
    wmma::fragment<wmma::matrix_b, 16, 16, 16, __half, wmma::col_major> bf0, bf1;

    int nch = (K + 127) >> 7;
    // prologue: stage chunks 0 and 1
    {
        int ke0 = (K < 128) ? K : 128;
        stage_chunk(smb + ABUF0, 0, ke0, s0, ld0, Kx, s1, m0);
        cp_async_commit();
        int ke1 = (K < 256) ? K : 256;
        stage_chunk(smb + ABUF0 + ABSZ, 128, ke1, s0, ld0, Kx, s1, m0);
        cp_async_commit();
    }
    int buf = 0;       // buffer of chunk i
    for (int i = 0; i < nch; ++i) {
        if (wB && i == 2) waitflag(wB, vB);
        if (i + 1 < nch) cp_async_wait1(); else cp_async_wait0();
        __syncthreads();
        if (i + 2 < nch) {
            int kb2 = (i + 2) << 7;
            int ke2 = kb2 + 128;
            if (ke2 > K) ke2 = K;
            int buf2 = buf + 2;
            if (buf2 >= 3) buf2 -= 3;
            stage_chunk(smb + ABUF0 + (uint32_t)buf2 * ABSZ, kb2, ke2, s0, ld0, Kx, s1, m0);
            cp_async_commit();
        }
        int kb = i << 7;
        int ke = kb + 128;
        if (ke > K) ke = K;
        const __half* abase = (const __half*)(smraw + ABUF0 + (size_t)buf * ABSZ)
                            + (size_t)(mi * 32) * ASTRH;
        const __half* bbase = (const __half*)smraw + (size_t)(ni * 32) * WSTRH + kb;
        int half = (ke - kb) >> 5;     // slabs per k-group: 4 (128 cols) or 2 (64 cols)
#pragma unroll 4
        for (int s = 0; s < half; ++s) {
            int kk = (kg * half + s) << 4;
            wmma::load_matrix_sync(af0, abase + kk, ASTRH);
            wmma::load_matrix_sync(af1, abase + 16 * ASTRH + kk, ASTRH);
            wmma::load_matrix_sync(bf0, bbase + kk, WSTRH);
            wmma::load_matrix_sync(bf1, bbase + 16 * WSTRH + kk, WSTRH);
            wmma::mma_sync(a00, af0, bf0, a00);
            wmma::mma_sync(a01, af0, bf1, a01);
            wmma::mma_sync(a10, af1, bf0, a10);
            wmma::mma_sync(a11, af1, bf1, a11);
        }
        buf = buf + 1;
        if (buf >= 3) buf = 0;
    }

    // k-group partials -> smf, reduce in epilogue
    float* smf = (float*)(smraw + SMFOFF) + (size_t)kg * 4096;
    wmma::store_matrix_sync(smf + (size_t)(mi * 32) * 64 + ni * 32,           a00, 64, wmma::mem_row_major);
    wmma::store_matrix_sync(smf + (size_t)(mi * 32) * 64 + ni * 32 + 16,      a01, 64, wmma::mem_row_major);
    wmma::store_matrix_sync(smf + (size_t)(mi * 32 + 16) * 64 + ni * 32,      a10, 64, wmma::mem_row_major);
    wmma::store_matrix_sync(smf + (size_t)(mi * 32 + 16) * 64 + ni * 32 + 16, a11, 64, wmma::mem_row_major);
    __syncthreads();
    if (wE) waitflag(wE, vE);

    const float* smf0 = (const float*)(smraw + SMFOFF);
    const float* smf1 = smf0 + 4096;
#pragma unroll
    for (int j = 0; j < 4; ++j) {
        int m = mb + 16 * j;
        float4 q0 = *(const float4*)(smf0 + (size_t)m * 64 + uloc * 4);
        float4 q1 = *(const float4*)(smf1 + (size_t)m * 64 + uloc * 4);
        float vi = q0.x + q1.x + badd[j * 4 + 0];
        float vf = q0.y + q1.y + badd[j * 4 + 1];
        float vg = q0.z + q1.z + badd[j * 4 + 2];
        float vo = q0.w + q1.w + badd[j * 4 + 3];
        float cn = sigf(vf) * cst[j] + sigf(vi) * tanhf(vg);
        float h  = sigf(vo) * tanhf(cn);
        cst[j] = cn;
        __half hh = __float2half(h);
        size_t off = (size_t)(m0 + m) * HID + u0 + uloc;
        hout[off] = hh;
        if (hsave) hsave[off] = hh;
    }
}

// ---------------- persistent wavefront kernel ----------------
__global__ __launch_bounds__(256, 1) void lstm_hmma() {
    extern __shared__ char smraw[];
    uint32_t smb = smem_to_u32(smraw);
    int tid = threadIdx.x;
    int w = tid >> 5;
    int cta = blockIdx.x;
    int lb = cta & 63;
    bool top = (cta >= 64);
    int mh = lb >> 5;
    int m0 = mh * 64;
    int u0 = (lb & 31) * 16;
    int kg = w & 1;
    int mi = (w >> 1) & 1;
    int ni = w >> 2;
    int uloc = tid & 15;
    int mb = tid >> 4;

    float badd[16];
    float cst[4];

    // ===== encoder =====
    if (!top) load_wsm(smraw, g_eWih0, INP, g_eWhh0, u0);
    else      load_wsm(smraw, g_eWih1, HID, g_eWhh1, u0);
    {
        const float* bias = top ? g_be1 : g_be0;
#pragma unroll
        for (int j = 0; j < 4; ++j)
#pragma unroll
            for (int g = 0; g < 4; ++g)
                badd[j * 4 + g] = bias[g * 512 + u0 + uloc];
    }
#pragma unroll
    for (int j = 0; j < 4; ++j) cst[j] = 0.f;
    __syncthreads();

    unsigned* fb = &g_flag[0 + mh];
    unsigned* ft = &g_flag[2 + mh];

    if (!top) {
        for (int t = 0; t < TT; ++t) {
            waitflag(fb, 32u * (unsigned)t);
            cell_step(smraw, smb, g_x16 + (size_t)t * BSZ * INP, INP, INP,
                      g_h0[(t + 1) & 1], INP + HID, badd, cst,
                      g_h0[t & 1], (__half*)0, m0, u0, kg, mi, ni, uloc, mb,
                      (unsigned*)0, 0u,
                      (t >= 2) ? ft : (unsigned*)0, 32u * (unsigned)(t - 1));
            post_flag(fb);
        }
    } else {
        for (int t = 0; t < TT; ++t) {
            waitflag(fb, 32u * (unsigned)(t + 1));
            cell_step(smraw, smb, g_h0[t & 1], HID, HID,
                      g_h1[(t + 1) & 1], 2 * HID, badd, cst,
                      g_h1[t & 1], (__half*)0, m0, u0, kg, mi, ni, uloc, mb,
                      ft, 32u * (unsigned)t,
                      (unsigned*)0, 0u);
            post_flag(ft);
        }
    }

    grid_sync(NCTA);

    // ===== gx = z @ dWih0^T (one-off; z = encoder h1 at t=127, parity 1) =====
    {
        wmma::fragment<wmma::accumulator, 16, 16, 16, float> acc1;
        wmma::fill_fragment(acc1, 0.f);
        wmma::fragment<wmma::matrix_a, 16, 16, 16, __half, wmma::row_major> af;
        wmma::fragment<wmma::matrix_b, 16, 16, 16, __half, wmma::col_major> bfx;
        const __half* ap = g_h1[1] + (size_t)(w * 16) * HID;
        const __half* bp = g_dWih0 + (size_t)(cta * 16) * HID;
#pragma unroll 4
        for (int k0 = 0; k0 < HID; k0 += 16) {
            wmma::load_matrix_sync(af, ap + k0, HID);
            wmma::load_matrix_sync(bfx, bp + k0, HID);
            wmma::mma_sync(acc1, af, bfx, acc1);
        }
        wmma::store_matrix_sync(g_gx + (size_t)(w * 16) * G4 + cta * 16, acc1,
                                G4, wmma::mem_row_major);
    }
    grid_sync(2 * NCTA);

    // ===== decoder =====
    if (!top) {
        load_wsm(smraw, (const __half*)0, 0, g_dWhh0, u0);
#pragma unroll
        for (int j = 0; j < 4; ++j)
#pragma unroll
            for (int g = 0; g < 4; ++g) {
                int colg = g * 512 + u0 + uloc;
                badd[j * 4 + g] = g_bd0[colg]
                                + g_gx[(size_t)(m0 + mb + 16 * j) * G4 + colg];
            }
    } else {
        load_wsm(smraw, g_dWih1, HID, g_dWhh1, u0);
#pragma unroll
        for (int j = 0; j < 4; ++j)
#pragma unroll
            for (int g = 0; g < 4; ++g)
                badd[j * 4 + g] = g_bd1[g * 512 + u0 + uloc];
    }
#pragma unroll
    for (int j = 0; j < 4; ++j) cst[j] = 0.f;
    __syncthreads();

    unsigned* fbd = &g_flag[4 + mh];
    unsigned* ftd = &g_flag[6 + mh];

    if (!top) {
        for (int t = 0; t < TT; ++t) {
            waitflag(fbd, 32u * (unsigned)t);
            cell_step(smraw, smb, (const __half*)0, 0, 0,
                      g_hd0[(t + 1) & 1], HID, badd, cst,
                      g_hd0[t & 1], (__half*)0, m0, u0, kg, mi, ni, uloc, mb,
                      (unsigned*)0, 0u,
                      (t >= 2) ? ftd : (unsigned*)0, 32u * (unsigned)(t - 1));
            post_flag(fbd);
        }
    } else {
        for (int t = 0; t < TT; ++t) {
            waitflag(fbd, 32u * (unsigned)(t + 1));
            cell_step(smraw, smb, g_hd0[t & 1], HID, HID,
                      g_hd1[(t + 1) & 1], 2 * HID, badd, cst,
                      g_hd1[t & 1], g_hs + (size_t)t * BSZ * HID,
                      m0, u0, kg, mi, ni, uloc, mb,
                      ftd, 32u * (unsigned)t,
                      (unsigned*)0, 0u);
            post_flag(ftd);
        }
    }
}

// ---------------- FC head ----------------
__global__ __launch_bounds__(128) void fc_kernel(const float* __restrict__ fcb,
                                                 float* __restrict__ out) {
    int m0 = blockIdx.x * 64;
    int w = threadIdx.x >> 5;

    wmma::fragment<wmma::accumulator, 16, 16, 16, float> acc[4];
#pragma unroll
    for (int mt = 0; mt < 4; mt++) wmma::fill_fragment(acc[mt], 0.f);
    wmma::fragment<wmma::matrix_a, 16, 16, 16, __half, wmma::row_major> af;
    wmma::fragment<wmma::matrix_b, 16, 16, 16, __half, wmma::col_major> bf;

    const __half* Wb = g_fcW + (size_t)(w * 16) * HID;
    for (int k0 = 0; k0 < HID; k0 += 16) {
        wmma::load_matrix_sync(bf, Wb + k0, HID);
#pragma unroll
        for (int mt = 0; mt < 4; mt++) {
            wmma::load_matrix_sync(af, g_hs + (size_t)(m0 + mt * 16) * HID + k0, HID);
            wmma::mma_sync(acc[mt], af, bf, acc[mt]);
        }
    }

    __shared__ float sm[64][64];
#pragma unroll
    for (int mt = 0; mt < 4; mt++) {
        wmma::store_matrix_sync(&sm[mt * 16][w * 16], acc[mt], 64, wmma::mem_row_major);
    }
    __syncthreads();

    for (int idx = threadIdx.x; idx < 4096; idx += 128) {
        int m = idx >> 6;
        int i = idx & 63;
        int gm = m0 + m;
        int b = gm & (BSZ - 1);
        int t = gm >> 7;
        out[(size_t)b * TT * INP + (size_t)t * INP + i] = sm[m][i] + fcb[i];
    }
}

// ---------------- launch ----------------
extern "C" void kernel_launch(void* const* d_in, const int* in_sizes, int n_in,
                              void* d_out, int out_size) {
    (void)in_sizes; (void)n_in; (void)out_size;
    const float* x      = (const float*)d_in[0];
    const float* eWih0  = (const float*)d_in[1];
    const float* eWhh0  = (const float*)d_in[2];
    const float* ebih0  = (const float*)d_in[3];
    const float* ebhh0  = (const float*)d_in[4];
    const float* eWih1  = (const float*)d_in[5];
    const float* eWhh1  = (const float*)d_in[6];
    const float* ebih1  = (const float*)d_in[7];
    const float* ebhh1  = (const float*)d_in[8];
    const float* dWih0  = (const float*)d_in[9];
    const float* dWhh0  = (const float*)d_in[10];
    const float* dbih0  = (const float*)d_in[11];
    const float* dbhh0  = (const float*)d_in[12];
    const float* dWih1  = (const float*)d_in[13];
    const float* dWhh1  = (const float*)d_in[14];
    const float* dbih1  = (const float*)d_in[15];
    const float* dbhh1  = (const float*)d_in[16];
    const float* fcW    = (const float*)d_in[17];
    const float* fcb    = (const float*)d_in[18];
    float* out = (float*)d_out;

    cudaFuncSetAttribute(lstm_hmma,
                         cudaFuncAttributeMaxDynamicSharedMemorySize, SMEM_TOTAL);

    prep_kernel<<<2048, 256>>>(x, eWih0, eWhh0, ebih0, ebhh0,
                               eWih1, eWhh1, ebih1, ebhh1,
                               dWih0, dWhh0, dbih0, dbhh0,
                               dWih1, dWhh1, dbih1, dbhh1, fcW);

    lstm_hmma<<<NCTA, 256, SMEM_TOTAL>>>();

    fc_kernel<<<256, 128>>>(fcb, out);
}